// round 5
// baseline (speedup 1.0000x reference)
#include <cuda_runtime.h>
#include <cstdint>
#include <cstddef>

#define S_LEN 2048
#define EMB   2048
#define NH    16
#define HD    128
#define NB    2
#define BHN   32            // NB*NH
#define MTOT  4096          // NB*S_LEN

#define BM 128
#define BN 128
#define BK 32
#define LDSM 36             // padded smem stride (floats): conflict-free frag loads

// Scratch (device globals: the sanctioned alloc-free scratch mechanism)
static __device__ float g_q [8388608];     // (B,H,S,D) rope'd q
static __device__ float g_k [8388608];     // (B,H,S,D) rope'd k
static __device__ float g_o [8388608];     // (B,S,E)   attention output (pre Wo)
static __device__ float g_sc[134217728];   // (B*H, S, S) scores / attn probs

__device__ __forceinline__ float tf32r(float x){
    unsigned u; asm("cvt.rna.tf32.f32 %0, %1;" : "=r"(u) : "f"(x));
    return __uint_as_float(u);
}

// ---------------------------------------------------------------------------
// Shared MMA core: consumes As[BM][LDSM], Bs[BN][LDSM] (both [row][k], tf32),
// accumulates C += A * B^T for one BK=32 slab.
// Warp layout: 8 warps, warp tile 64(M) x 32(N); per warp 4x4 m16n8k8 tiles.
// ---------------------------------------------------------------------------
__device__ __forceinline__ void mma_tile(const float* As, const float* Bs,
                                         float (&c)[4][4][4], int lane, int wm, int wn)
{
    const int g = lane >> 2, t = lane & 3;
#pragma unroll
    for (int ks = 0; ks < 4; ks++){
        const int k0 = ks * 8;
        unsigned a[4][4], b[4][2];
#pragma unroll
        for (int im = 0; im < 4; im++){
            const int r0 = (wm + im*16 + g) * LDSM;
            a[im][0] = __float_as_uint(As[r0          + k0 + t    ]);
            a[im][1] = __float_as_uint(As[r0 + 8*LDSM + k0 + t    ]);
            a[im][2] = __float_as_uint(As[r0          + k0 + t + 4]);
            a[im][3] = __float_as_uint(As[r0 + 8*LDSM + k0 + t + 4]);
        }
#pragma unroll
        for (int in_ = 0; in_ < 4; in_++){
            const int nr = (wn + in_*8 + g) * LDSM;
            b[in_][0] = __float_as_uint(Bs[nr + k0 + t    ]);
            b[in_][1] = __float_as_uint(Bs[nr + k0 + t + 4]);
        }
#pragma unroll
        for (int im = 0; im < 4; im++)
#pragma unroll
            for (int in_ = 0; in_ < 4; in_++)
                asm volatile(
                    "mma.sync.aligned.m16n8k8.row.col.f32.tf32.tf32.f32 "
                    "{%0,%1,%2,%3}, {%4,%5,%6,%7}, {%8,%9}, {%0,%1,%2,%3};\n"
                    : "+f"(c[im][in_][0]), "+f"(c[im][in_][1]),
                      "+f"(c[im][in_][2]), "+f"(c[im][in_][3])
                    : "r"(a[im][0]), "r"(a[im][1]), "r"(a[im][2]), "r"(a[im][3]),
                      "r"(b[in_][0]), "r"(b[in_][1]));
    }
}

#define ZERO_C(c) \
    _Pragma("unroll") for (int zi=0; zi<4; zi++) \
    _Pragma("unroll") for (int zj=0; zj<4; zj++) \
    _Pragma("unroll") for (int zr=0; zr<4; zr++) c[zi][zj][zr] = 0.f;

// ---------------------------------------------------------------------------
// 1) Fused QKV projection: y[b,s,o] = sum_e x[b,s,e] * W[o,e]  (grid.z: q/k/v)
//    Writes (B,H,S,D) layout: q -> g_q, k -> d_out k-region, v -> d_out v-region
// ---------------------------------------------------------------------------
__global__ void __launch_bounds__(256) qkv_kernel(
    const float* __restrict__ x, const float* __restrict__ Wq,
    const float* __restrict__ Wk, const float* __restrict__ Wv,
    float* __restrict__ kout, float* __restrict__ vout)
{
    __shared__ float As[BM*LDSM];
    __shared__ float Bs[BN*LDSM];
    const int tid = threadIdx.x;
    const int n0 = blockIdx.x*BN, m0 = blockIdx.y*BM, widx = blockIdx.z;
    const float* __restrict__ Wp = (widx==0)?Wq:((widx==1)?Wk:Wv);
    const int lane = tid & 31, w = tid >> 5;
    const int wm = (w>>2)*64, wn = (w&3)*32;
    const int lr = tid >> 3, lc = (tid & 7) << 2;
    float c[4][4][4]; ZERO_C(c);

    float4 ra[4], rb[4];
#pragma unroll
    for (int i=0;i<4;i++){
        ra[i] = *(const float4*)&x [(size_t)(m0+lr+i*32)*EMB + lc];
        rb[i] = *(const float4*)&Wp[(size_t)(n0+lr+i*32)*EMB + lc];
    }
    for (int kk=0; kk<EMB; kk+=BK){
#pragma unroll
        for (int i=0;i<4;i++){
            const int r = lr + i*32;
            *(float4*)&As[r*LDSM+lc] = make_float4(tf32r(ra[i].x),tf32r(ra[i].y),tf32r(ra[i].z),tf32r(ra[i].w));
            *(float4*)&Bs[r*LDSM+lc] = make_float4(tf32r(rb[i].x),tf32r(rb[i].y),tf32r(rb[i].z),tf32r(rb[i].w));
        }
        __syncthreads();
        if (kk + BK < EMB){
#pragma unroll
            for (int i=0;i<4;i++){
                ra[i] = *(const float4*)&x [(size_t)(m0+lr+i*32)*EMB + kk+BK + lc];
                rb[i] = *(const float4*)&Wp[(size_t)(n0+lr+i*32)*EMB + kk+BK + lc];
            }
        }
        mma_tile(As,Bs,c,lane,wm,wn);
        __syncthreads();
    }
    const int g = lane>>2, t = lane&3;
#pragma unroll
    for (int im=0;im<4;im++)
#pragma unroll
    for (int in_=0;in_<4;in_++)
#pragma unroll
    for (int r=0;r<4;r++){
        const int row = m0 + wm + im*16 + g + ((r&2)?8:0);
        const int col = n0 + wn + in_*8 + 2*t + (r&1);
        const int b = row >> 11, s = row & (S_LEN-1);
        const int h = col >> 7,  d = col & (HD-1);
        const size_t dst = (((size_t)(b*NH+h))*S_LEN + s)*HD + d;
        const float v = c[im][in_][r];
        if      (widx==0) g_q[dst] = v;
        else if (widx==1) kout[dst] = v;
        else              vout[dst] = v;
    }
}

// ---------------------------------------------------------------------------
// 2) RoPE: in-place on g_q; kin (raw k in d_out) -> g_k (rope'd).
//    Double-precision angle reduction so accuracy is compile-flag independent.
// ---------------------------------------------------------------------------
__global__ void __launch_bounds__(256) rope_kernel(const float* __restrict__ kin)
{
    const int idx = blockIdx.x*256 + threadIdx.x;      // < B*H*S*(D/2)
    const int j  = idx & 63;
    const int s  = (idx >> 6) & (S_LEN-1);
    const int bh = idx >> 17;
    const float e = (float)(2*j) * (1.0f/128.0f);
    const float invf = (float)exp2(-(double)e * 13.287712379549449); // 10000^-e
    const float ang  = (float)s * invf;
    const double angd = (double)ang;
    const double kq = rint(angd * 0.15915494309189535);  // 1/(2*pi)
    const float rr = (float)(angd - kq * 6.283185307179586);
    float sn, cs;
    __sincosf(rr, &sn, &cs);
    const size_t base = (((size_t)bh)*S_LEN + s)*HD + 2*j;
    float x1 = g_q[base], x2 = g_q[base+1];
    g_q[base]   = x1*cs - x2*sn;
    g_q[base+1] = x1*sn + x2*cs;
    x1 = kin[base]; x2 = kin[base+1];
    g_k[base]   = x1*cs - x2*sn;
    g_k[base+1] = x1*sn + x2*cs;
}

// ---------------------------------------------------------------------------
// 3) Causal scores: per (b,h): S = (q_rot @ k_rot^T) / sqrt(D); only blocks
//    with n0 <= m0 computed; only elements col<=row written.
// ---------------------------------------------------------------------------
__global__ void __launch_bounds__(256) scores_kernel()
{
    const int n0 = blockIdx.x*BN, m0 = blockIdx.y*BM, bh = blockIdx.z;
    if (n0 > m0) return;
    __shared__ float As[BM*LDSM];
    __shared__ float Bs[BN*LDSM];
    const int tid = threadIdx.x;
    const int lane = tid & 31, w = tid >> 5;
    const int wm = (w>>2)*64, wn = (w&3)*32;
    const int lr = tid >> 3, lc = (tid & 7) << 2;
    const float* __restrict__ A  = g_q + (size_t)bh*S_LEN*HD;
    const float* __restrict__ Bp = g_k + (size_t)bh*S_LEN*HD;
    float c[4][4][4]; ZERO_C(c);

    float4 ra[4], rb[4];
#pragma unroll
    for (int i=0;i<4;i++){
        ra[i] = *(const float4*)&A [(size_t)(m0+lr+i*32)*HD + lc];
        rb[i] = *(const float4*)&Bp[(size_t)(n0+lr+i*32)*HD + lc];
    }
#pragma unroll
    for (int kk=0; kk<HD; kk+=BK){
#pragma unroll
        for (int i=0;i<4;i++){
            const int r = lr + i*32;
            *(float4*)&As[r*LDSM+lc] = make_float4(tf32r(ra[i].x),tf32r(ra[i].y),tf32r(ra[i].z),tf32r(ra[i].w));
            *(float4*)&Bs[r*LDSM+lc] = make_float4(tf32r(rb[i].x),tf32r(rb[i].y),tf32r(rb[i].z),tf32r(rb[i].w));
        }
        __syncthreads();
        if (kk + BK < HD){
#pragma unroll
            for (int i=0;i<4;i++){
                ra[i] = *(const float4*)&A [(size_t)(m0+lr+i*32)*HD + kk+BK + lc];
                rb[i] = *(const float4*)&Bp[(size_t)(n0+lr+i*32)*HD + kk+BK + lc];
            }
        }
        mma_tile(As,Bs,c,lane,wm,wn);
        __syncthreads();
    }
    const int g = lane>>2, t = lane&3;
    const float scale = 0.08838834764831843f;  // 1/sqrt(128)
#pragma unroll
    for (int im=0;im<4;im++)
#pragma unroll
    for (int in_=0;in_<4;in_++)
#pragma unroll
    for (int r=0;r<4;r++){
        const int row = m0 + wm + im*16 + g + ((r&2)?8:0);
        const int col = n0 + wn + in_*8 + 2*t + (r&1);
        if (col <= row)
            g_sc[((size_t)bh*S_LEN + row)*S_LEN + col] = c[im][in_][r]*scale;
    }
}

// ---------------------------------------------------------------------------
// 4) Row softmax over causal prefix; zero-fills the tail of the diagonal
//    128-block so PV can read clean 128-wide K tiles.
// ---------------------------------------------------------------------------
__global__ void __launch_bounds__(256) softmax_kernel()
{
    __shared__ float red[8];
    const int tid = threadIdx.x;
    const int idx = blockIdx.x;                 // bh*S + q
    const int q = idx & (S_LEN-1);
    float* __restrict__ row = g_sc + (size_t)idx * S_LEN;
    const int L = q + 1;
    const int Lpad = ((q >> 7) + 1) << 7;
    float v[8];
    float mx = -3.0e38f;
#pragma unroll
    for (int i=0;i<8;i++){
        const int cidx = i*256 + tid;
        v[i] = (cidx < L) ? row[cidx] : -3.0e38f;
        mx = fmaxf(mx, v[i]);
    }
#pragma unroll
    for (int o=16;o;o>>=1) mx = fmaxf(mx, __shfl_xor_sync(0xffffffffu, mx, o));
    if ((tid&31)==0) red[tid>>5] = mx;
    __syncthreads();
    mx = fmaxf(fmaxf(fmaxf(red[0],red[1]),fmaxf(red[2],red[3])),
               fmaxf(fmaxf(red[4],red[5]),fmaxf(red[6],red[7])));
    float ssum = 0.f;
#pragma unroll
    for (int i=0;i<8;i++){
        const int cidx = i*256 + tid;
        if (cidx < L){ v[i] = expf(v[i]-mx); ssum += v[i]; }
    }
#pragma unroll
    for (int o=16;o;o>>=1) ssum += __shfl_xor_sync(0xffffffffu, ssum, o);
    __syncthreads();
    if ((tid&31)==0) red[tid>>5] = ssum;
    __syncthreads();
    const float tot = red[0]+red[1]+red[2]+red[3]+red[4]+red[5]+red[6]+red[7];
    const float inv = 1.0f / tot;
#pragma unroll
    for (int i=0;i<8;i++){
        const int cidx = i*256 + tid;
        if (cidx < L)          row[cidx] = v[i]*inv;
        else if (cidx < Lpad)  row[cidx] = 0.f;
    }
}

// ---------------------------------------------------------------------------
// 5) PV: per (b,h): O = attn @ V. K range causally clipped to m0+128.
//    Epilogue writes directly into (B,S,E) so out-proj is a plain GEMM.
// ---------------------------------------------------------------------------
__global__ void __launch_bounds__(256) pv_kernel(const float* __restrict__ vsrc)
{
    const int m0 = blockIdx.y*BM, bh = blockIdx.z;
    __shared__ float As[BM*LDSM];
    __shared__ float Bs[BN*LDSM];
    const int tid = threadIdx.x;
    const int lane = tid & 31, w = tid >> 5;
    const int wm = (w>>2)*64, wn = (w&3)*32;
    const int lr = tid >> 3, lc = (tid & 7) << 2;       // A loader (K-major)
    const int bkr = tid >> 5, bn4 = (tid & 31) << 2;    // B loader (N-major rows)
    const float* __restrict__ A = g_sc + (size_t)bh*S_LEN*S_LEN;
    const float* __restrict__ V = vsrc + (size_t)bh*S_LEN*HD;
    const int kmax = m0 + BM;
    float c[4][4][4]; ZERO_C(c);

    float4 ra[4], rb[4];
#pragma unroll
    for (int i=0;i<4;i++){
        ra[i] = *(const float4*)&A[(size_t)(m0+lr+i*32)*S_LEN + lc];
        rb[i] = *(const float4*)&V[(size_t)(bkr+i*8)*HD + bn4];
    }
    for (int kk=0; kk<kmax; kk+=BK){
#pragma unroll
        for (int i=0;i<4;i++){
            const int r = lr + i*32;
            *(float4*)&As[r*LDSM+lc] = make_float4(tf32r(ra[i].x),tf32r(ra[i].y),tf32r(ra[i].z),tf32r(ra[i].w));
            const int kr = bkr + i*8;
            Bs[(bn4+0)*LDSM+kr] = tf32r(rb[i].x);
            Bs[(bn4+1)*LDSM+kr] = tf32r(rb[i].y);
            Bs[(bn4+2)*LDSM+kr] = tf32r(rb[i].z);
            Bs[(bn4+3)*LDSM+kr] = tf32r(rb[i].w);
        }
        __syncthreads();
        if (kk + BK < kmax){
#pragma unroll
            for (int i=0;i<4;i++){
                ra[i] = *(const float4*)&A[(size_t)(m0+lr+i*32)*S_LEN + kk+BK + lc];
                rb[i] = *(const float4*)&V[(size_t)(kk+BK+bkr+i*8)*HD + bn4];
            }
        }
        mma_tile(As,Bs,c,lane,wm,wn);
        __syncthreads();
    }
    const int g = lane>>2, t = lane&3;
    const int b = bh >> 4, h = bh & 15;
#pragma unroll
    for (int im=0;im<4;im++)
#pragma unroll
    for (int in_=0;in_<4;in_++)
#pragma unroll
    for (int r=0;r<4;r++){
        const int row = m0 + wm + im*16 + g + ((r&2)?8:0);
        const int col = wn + in_*8 + 2*t + (r&1);
        g_o[((size_t)b*S_LEN + row)*EMB + h*HD + col] = c[im][in_][r];
    }
}

// ---------------------------------------------------------------------------
// 6) Output projection: attn_out = O @ Wo^T  ->  d_out[0 : B*S*E]
// ---------------------------------------------------------------------------
__global__ void __launch_bounds__(256) oproj_kernel(const float* __restrict__ Wo,
                                                    float* __restrict__ out)
{
    __shared__ float As[BM*LDSM];
    __shared__ float Bs[BN*LDSM];
    const int tid = threadIdx.x;
    const int n0 = blockIdx.x*BN, m0 = blockIdx.y*BM;
    const int lane = tid & 31, w = tid >> 5;
    const int wm = (w>>2)*64, wn = (w&3)*32;
    const int lr = tid >> 3, lc = (tid & 7) << 2;
    float c[4][4][4]; ZERO_C(c);

    float4 ra[4], rb[4];
#pragma unroll
    for (int i=0;i<4;i++){
        ra[i] = *(const float4*)&g_o[(size_t)(m0+lr+i*32)*EMB + lc];
        rb[i] = *(const float4*)&Wo [(size_t)(n0+lr+i*32)*EMB + lc];
    }
    for (int kk=0; kk<EMB; kk+=BK){
#pragma unroll
        for (int i=0;i<4;i++){
            const int r = lr + i*32;
            *(float4*)&As[r*LDSM+lc] = make_float4(tf32r(ra[i].x),tf32r(ra[i].y),tf32r(ra[i].z),tf32r(ra[i].w));
            *(float4*)&Bs[r*LDSM+lc] = make_float4(tf32r(rb[i].x),tf32r(rb[i].y),tf32r(rb[i].z),tf32r(rb[i].w));
        }
        __syncthreads();
        if (kk + BK < EMB){
#pragma unroll
            for (int i=0;i<4;i++){
                ra[i] = *(const float4*)&g_o[(size_t)(m0+lr+i*32)*EMB + kk+BK + lc];
                rb[i] = *(const float4*)&Wo [(size_t)(n0+lr+i*32)*EMB + kk+BK + lc];
            }
        }
        mma_tile(As,Bs,c,lane,wm,wn);
        __syncthreads();
    }
    const int g = lane>>2, t = lane&3;
#pragma unroll
    for (int im=0;im<4;im++)
#pragma unroll
    for (int in_=0;in_<4;in_++)
#pragma unroll
    for (int r=0;r<4;r++){
        const int row = m0 + wm + im*16 + g + ((r&2)?8:0);
        const int col = n0 + wn + in_*8 + 2*t + (r&1);
        out[(size_t)row*EMB + col] = c[im][in_][r];
    }
}

// ---------------------------------------------------------------------------
extern "C" void kernel_launch(void* const* d_in, const int* in_sizes, int n_in,
                              void* d_out, int out_size)
{
    (void)in_sizes; (void)n_in; (void)out_size;
    const float* x  = (const float*)d_in[0];
    const float* Wq = (const float*)d_in[1];
    const float* Wk = (const float*)d_in[2];
    const float* Wv = (const float*)d_in[3];
    const float* Wo = (const float*)d_in[4];
    float* out  = (float*)d_out;                    // attn_out (B,S,E)
    float* kout = out  + (size_t)8388608;           // k (B,H,S,D)
    float* vout = kout + (size_t)8388608;           // v (B,H,S,D)

    qkv_kernel   <<<dim3(EMB/BN, MTOT/BM, 3), 256>>>(x, Wq, Wk, Wv, kout, vout);
    rope_kernel  <<<16384, 256>>>(kout);
    scores_kernel<<<dim3(S_LEN/BN, S_LEN/BM, BHN), 256>>>();
    softmax_kernel<<<BHN*S_LEN, 256>>>();
    pv_kernel    <<<dim3(1, S_LEN/BM, BHN), 256>>>(vout);
    oproj_kernel <<<dim3(EMB/BN, MTOT/BM), 256>>>(Wo, out);
}

// round 9
// speedup vs baseline: 1.0413x; 1.0413x over previous
#include <cuda_runtime.h>
#include <cstdint>
#include <cstddef>

#define S_LEN 2048
#define EMB   2048
#define NH    16
#define HD    128
#define NB    2
#define BHN   32            // NB*NH
#define MTOT  4096          // NB*S_LEN

#define BM 128
#define BN 128
#define BK 32
#define LDSM 36             // padded smem stride (floats): conflict-free frag loads

// Scratch (device globals: the sanctioned alloc-free scratch mechanism)
static __device__ float g_q [8388608];     // (B,H,S,D) rope'd q
static __device__ float g_k [8388608];     // (B,H,S,D) rope'd k
static __device__ float g_o [8388608];     // (B,S,E)   attention out (pre Wo), tf32-rounded
static __device__ float g_x [8388608];     // tf32-rounded x
static __device__ float g_wr[16777216];    // tf32-rounded Wq|Wk|Wv|Wo (4.19M each)
static __device__ float g_sc[134217728];   // (B*H, S, S) scores / attn probs

__device__ __forceinline__ float tf32r(float x){
    unsigned u; asm("cvt.rna.tf32.f32 %0, %1;" : "=r"(u) : "f"(x));
    return __uint_as_float(u);
}
__device__ __forceinline__ float4 tf4(float4 v){
    return make_float4(tf32r(v.x), tf32r(v.y), tf32r(v.z), tf32r(v.w));
}
__device__ __forceinline__ uint32_t smem_u32(const void* p){
    uint32_t a;
    asm("{ .reg .u64 t; cvta.to.shared.u64 t, %1; cvt.u32.u64 %0, t; }" : "=r"(a) : "l"(p));
    return a;
}

// ---------------------------------------------------------------------------
// Shared MMA core: consumes As[128][36], Bs[128][36] ([row][k], tf32),
// accumulates C += A * B^T for one BK=32 slab.
// 8 warps, warp tile 64(M) x 32(N); per warp 4x4 m16n8k8 tiles.
// ---------------------------------------------------------------------------
__device__ __forceinline__ void mma_tile(const float* As, const float* Bs,
                                         float (&c)[4][4][4], int lane, int wm, int wn)
{
    const int g = lane >> 2, t = lane & 3;
#pragma unroll
    for (int ks = 0; ks < 4; ks++){
        const int k0 = ks * 8;
        unsigned a[4][4], b[4][2];
#pragma unroll
        for (int im = 0; im < 4; im++){
            const int r0 = (wm + im*16 + g) * LDSM;
            a[im][0] = __float_as_uint(As[r0          + k0 + t    ]);
            a[im][1] = __float_as_uint(As[r0 + 8*LDSM + k0 + t    ]);
            a[im][2] = __float_as_uint(As[r0          + k0 + t + 4]);
            a[im][3] = __float_as_uint(As[r0 + 8*LDSM + k0 + t + 4]);
        }
#pragma unroll
        for (int in_ = 0; in_ < 4; in_++){
            const int nr = (wn + in_*8 + g) * LDSM;
            b[in_][0] = __float_as_uint(Bs[nr + k0 + t    ]);
            b[in_][1] = __float_as_uint(Bs[nr + k0 + t + 4]);
        }
#pragma unroll
        for (int im = 0; im < 4; im++)
#pragma unroll
            for (int in_ = 0; in_ < 4; in_++)
                asm volatile(
                    "mma.sync.aligned.m16n8k8.row.col.f32.tf32.tf32.f32 "
                    "{%0,%1,%2,%3}, {%4,%5,%6,%7}, {%8,%9}, {%0,%1,%2,%3};\n"
                    : "+f"(c[im][in_][0]), "+f"(c[im][in_][1]),
                      "+f"(c[im][in_][2]), "+f"(c[im][in_][3])
                    : "r"(a[im][0]), "r"(a[im][1]), "r"(a[im][2]), "r"(a[im][3]),
                      "r"(b[in_][0]), "r"(b[in_][1]));
    }
}

#define ZERO_C(c) \
    _Pragma("unroll") for (int zi=0; zi<4; zi++) \
    _Pragma("unroll") for (int zj=0; zj<4; zj++) \
    _Pragma("unroll") for (int zr=0; zr<4; zr++) c[zi][zj][zr] = 0.f;

// ===========================================================================
// v2 projection-GEMM core: C[128,128] = A[128,2048] * B[128,2048]^T
// Inputs pre-rounded to tf32. cp.async 3-stage pipeline, one barrier/slab,
// 2 CTAs/SM. smem stage = A(18432B) + B(18432B); 3 stages = 110592B.
// ===========================================================================
#define V2_STG_A 18432
#define V2_STG   36864
#define V2_SMEM  110592
#define V2_NKT   64

__device__ __forceinline__ void cp16(uint32_t dst, const float* src){
    asm volatile("cp.async.cg.shared.global [%0], [%1], 16;" :: "r"(dst), "l"(src) : "memory");
}
__device__ __forceinline__ void cp_commit(){ asm volatile("cp.async.commit_group;" ::: "memory"); }
__device__ __forceinline__ void cp_wait1(){ asm volatile("cp.async.wait_group 1;" ::: "memory"); }

__device__ __forceinline__ void v2_issue(uint32_t sbase, int stage,
                                         const float* Ap, const float* Bp, int tid){
    const uint32_t sa = sbase + stage * V2_STG;
    const uint32_t sb = sa + V2_STG_A;
#pragma unroll
    for (int i = 0; i < 4; i++){
        const int idx = tid + i * 256;
        const int row = idx >> 3, c4 = idx & 7;
        cp16(sa + row*144 + c4*16, Ap + (size_t)row * EMB + c4*4);
        cp16(sb + row*144 + c4*16, Bp + (size_t)row * EMB + c4*4);
    }
}

__device__ __forceinline__ void v2_mainloop(const float* __restrict__ A,
                                            const float* __restrict__ B,
                                            float (&c)[4][4][4], char* smem,
                                            int tid, int lane, int wm, int wn)
{
    const uint32_t sbase = smem_u32(smem);
    v2_issue(sbase, 0, A,       B,       tid); cp_commit();
    v2_issue(sbase, 1, A + BK,  B + BK,  tid); cp_commit();
    int st = 0, st2 = 2;
    for (int kt = 0; kt < V2_NKT; kt++){
        cp_wait1();                 // stage kt resident
        __syncthreads();
        const float* As = (const float*)(smem + st * V2_STG);
        const float* Bs = As + V2_STG_A / 4;
        mma_tile(As, Bs, c, lane, wm, wn);
        if (kt + 2 < V2_NKT)
            v2_issue(sbase, st2, A + (kt+2)*BK, B + (kt+2)*BK, tid);
        cp_commit();                // empty group at tail keeps wait math uniform
        st  = (st  == 2) ? 0 : st  + 1;
        st2 = (st2 == 2) ? 0 : st2 + 1;
    }
}

// ---------------------------------------------------------------------------
// 0) Pre-round fp32 -> tf32 (rna), float4 granularity.
// ---------------------------------------------------------------------------
__global__ void __launch_bounds__(256) preround_kernel(const float4* __restrict__ src,
                                                       float4* __restrict__ dst)
{
    const int i = blockIdx.x * 256 + threadIdx.x;
    dst[i] = tf4(src[i]);
}

// ---------------------------------------------------------------------------
// 1) QKV projection (grid.z selects W). Writes (B,H,S,D):
//    q -> g_q, k -> d_out k-region, v -> d_out v-region.
// ---------------------------------------------------------------------------
__global__ void __launch_bounds__(256,2) qkv2_kernel(float* __restrict__ kout,
                                                     float* __restrict__ vout)
{
    extern __shared__ char smem[];
    const int tid = threadIdx.x, lane = tid & 31, w = tid >> 5;
    const int wm = (w>>2)*64, wn = (w&3)*32;
    const int n0 = blockIdx.x*BN, m0 = blockIdx.y*BM, widx = blockIdx.z;
    const float* A = g_x  + (size_t)m0 * EMB;
    const float* B = g_wr + (size_t)widx * 4194304 + (size_t)n0 * EMB;
    float c[4][4][4]; ZERO_C(c);
    v2_mainloop(A, B, c, smem, tid, lane, wm, wn);

    const int g = lane>>2, t = lane&3;
#pragma unroll
    for (int im=0;im<4;im++)
#pragma unroll
    for (int in_=0;in_<4;in_++)
#pragma unroll
    for (int r=0;r<4;r++){
        const int row = m0 + wm + im*16 + g + ((r&2)?8:0);
        const int col = n0 + wn + in_*8 + 2*t + (r&1);
        const int b = row >> 11, s = row & (S_LEN-1);
        const int h = col >> 7,  d = col & (HD-1);
        const size_t dst = (((size_t)(b*NH+h))*S_LEN + s)*HD + d;
        const float v = c[im][in_][r];
        if      (widx==0) g_q[dst] = v;
        else if (widx==1) kout[dst] = v;
        else              vout[dst] = v;
    }
}

// ---------------------------------------------------------------------------
// 6) Output projection: attn_out = g_o @ Wo^T -> d_out[0 : B*S*E]
// ---------------------------------------------------------------------------
__global__ void __launch_bounds__(256,2) oproj2_kernel(float* __restrict__ out)
{
    extern __shared__ char smem[];
    const int tid = threadIdx.x, lane = tid & 31, w = tid >> 5;
    const int wm = (w>>2)*64, wn = (w&3)*32;
    const int n0 = blockIdx.x*BN, m0 = blockIdx.y*BM;
    const float* A = g_o  + (size_t)m0 * EMB;
    const float* B = g_wr + (size_t)12582912 + (size_t)n0 * EMB;
    float c[4][4][4]; ZERO_C(c);
    v2_mainloop(A, B, c, smem, tid, lane, wm, wn);

    const int g = lane>>2, t = lane&3;
#pragma unroll
    for (int im=0;im<4;im++)
#pragma unroll
    for (int in_=0;in_<4;in_++)
#pragma unroll
    for (int r=0;r<4;r++){
        const int row = m0 + wm + im*16 + g + ((r&2)?8:0);
        const int col = n0 + wn + in_*8 + 2*t + (r&1);
        out[(size_t)row*EMB + col] = c[im][in_][r];
    }
}

// ---------------------------------------------------------------------------
// 2) RoPE: in-place on g_q; kin (raw k in d_out) -> g_k (rope'd).
// ---------------------------------------------------------------------------
__global__ void __launch_bounds__(256) rope_kernel(const float* __restrict__ kin)
{
    const int idx = blockIdx.x*256 + threadIdx.x;      // < B*H*S*(D/2)
    const int j  = idx & 63;
    const int s  = (idx >> 6) & (S_LEN-1);
    const int bh = idx >> 17;
    const float e = (float)(2*j) * (1.0f/128.0f);
    const float invf = (float)exp2(-(double)e * 13.287712379549449); // 10000^-e
    const float ang  = (float)s * invf;
    const double angd = (double)ang;
    const double kq = rint(angd * 0.15915494309189535);  // 1/(2*pi)
    const float rr = (float)(angd - kq * 6.283185307179586);
    float sn, cs;
    __sincosf(rr, &sn, &cs);
    const size_t base = (((size_t)bh)*S_LEN + s)*HD + 2*j;
    float x1 = g_q[base], x2 = g_q[base+1];
    g_q[base]   = x1*cs - x2*sn;
    g_q[base+1] = x1*sn + x2*cs;
    x1 = kin[base]; x2 = kin[base+1];
    g_k[base]   = x1*cs - x2*sn;
    g_k[base+1] = x1*sn + x2*cs;
}

// ---------------------------------------------------------------------------
// 3) Causal scores: per (b,h): S = (q_rot @ k_rot^T) / sqrt(D)
// ---------------------------------------------------------------------------
__global__ void __launch_bounds__(256) scores_kernel()
{
    const int n0 = blockIdx.x*BN, m0 = blockIdx.y*BM, bh = blockIdx.z;
    if (n0 > m0) return;
    __shared__ float As[BM*LDSM];
    __shared__ float Bs[BN*LDSM];
    const int tid = threadIdx.x;
    const int lane = tid & 31, w = tid >> 5;
    const int wm = (w>>2)*64, wn = (w&3)*32;
    const int lr = tid >> 3, lc = (tid & 7) << 2;
    const float* __restrict__ A  = g_q + (size_t)bh*S_LEN*HD;
    const float* __restrict__ Bp = g_k + (size_t)bh*S_LEN*HD;
    float c[4][4][4]; ZERO_C(c);

    float4 ra[4], rb[4];
#pragma unroll
    for (int i=0;i<4;i++){
        ra[i] = *(const float4*)&A [(size_t)(m0+lr+i*32)*HD + lc];
        rb[i] = *(const float4*)&Bp[(size_t)(n0+lr+i*32)*HD + lc];
    }
#pragma unroll
    for (int kk=0; kk<HD; kk+=BK){
#pragma unroll
        for (int i=0;i<4;i++){
            const int r = lr + i*32;
            *(float4*)&As[r*LDSM+lc] = make_float4(tf32r(ra[i].x),tf32r(ra[i].y),tf32r(ra[i].z),tf32r(ra[i].w));
            *(float4*)&Bs[r*LDSM+lc] = make_float4(tf32r(rb[i].x),tf32r(rb[i].y),tf32r(rb[i].z),tf32r(rb[i].w));
        }
        __syncthreads();
        if (kk + BK < HD){
#pragma unroll
            for (int i=0;i<4;i++){
                ra[i] = *(const float4*)&A [(size_t)(m0+lr+i*32)*HD + kk+BK + lc];
                rb[i] = *(const float4*)&Bp[(size_t)(n0+lr+i*32)*HD + kk+BK + lc];
            }
        }
        mma_tile(As,Bs,c,lane,wm,wn);
        __syncthreads();
    }
    const int g = lane>>2, t = lane&3;
    const float scale = 0.08838834764831843f;  // 1/sqrt(128)
#pragma unroll
    for (int im=0;im<4;im++)
#pragma unroll
    for (int in_=0;in_<4;in_++)
#pragma unroll
    for (int r=0;r<4;r++){
        const int row = m0 + wm + im*16 + g + ((r&2)?8:0);
        const int col = n0 + wn + in_*8 + 2*t + (r&1);
        if (col <= row)
            g_sc[((size_t)bh*S_LEN + row)*S_LEN + col] = c[im][in_][r]*scale;
    }
}

// ---------------------------------------------------------------------------
// 4) Row softmax over causal prefix; zero-fills diagonal-block tail.
// ---------------------------------------------------------------------------
__global__ void __launch_bounds__(256) softmax_kernel()
{
    __shared__ float red[8];
    const int tid = threadIdx.x;
    const int idx = blockIdx.x;                 // bh*S + q
    const int q = idx & (S_LEN-1);
    float* __restrict__ row = g_sc + (size_t)idx * S_LEN;
    const int L = q + 1;
    const int Lpad = ((q >> 7) + 1) << 7;
    float v[8];
    float mx = -3.0e38f;
#pragma unroll
    for (int i=0;i<8;i++){
        const int cidx = i*256 + tid;
        v[i] = (cidx < L) ? row[cidx] : -3.0e38f;
        mx = fmaxf(mx, v[i]);
    }
#pragma unroll
    for (int o=16;o;o>>=1) mx = fmaxf(mx, __shfl_xor_sync(0xffffffffu, mx, o));
    if ((tid&31)==0) red[tid>>5] = mx;
    __syncthreads();
    mx = fmaxf(fmaxf(fmaxf(red[0],red[1]),fmaxf(red[2],red[3])),
               fmaxf(fmaxf(red[4],red[5]),fmaxf(red[6],red[7])));
    float ssum = 0.f;
#pragma unroll
    for (int i=0;i<8;i++){
        const int cidx = i*256 + tid;
        if (cidx < L){ v[i] = expf(v[i]-mx); ssum += v[i]; }
    }
#pragma unroll
    for (int o=16;o;o>>=1) ssum += __shfl_xor_sync(0xffffffffu, ssum, o);
    __syncthreads();
    if ((tid&31)==0) red[tid>>5] = ssum;
    __syncthreads();
    const float tot = red[0]+red[1]+red[2]+red[3]+red[4]+red[5]+red[6]+red[7];
    const float inv = 1.0f / tot;
#pragma unroll
    for (int i=0;i<8;i++){
        const int cidx = i*256 + tid;
        if (cidx < L)          row[cidx] = v[i]*inv;
        else if (cidx < Lpad)  row[cidx] = 0.f;
    }
}

// ---------------------------------------------------------------------------
// 5) PV: per (b,h): O = attn @ V, K clipped to m0+128. Writes tf32-rounded
//    g_o (B,S,E) so oproj2 can cp.async it raw (numerics identical to
//    rounding at oproj load).
// ---------------------------------------------------------------------------
__global__ void __launch_bounds__(256) pv_kernel(const float* __restrict__ vsrc)
{
    const int m0 = blockIdx.y*BM, bh = blockIdx.z;
    __shared__ float As[BM*LDSM];
    __shared__ float Bs[BN*LDSM];
    const int tid = threadIdx.x;
    const int lane = tid & 31, w = tid >> 5;
    const int wm = (w>>2)*64, wn = (w&3)*32;
    const int lr = tid >> 3, lc = (tid & 7) << 2;       // A loader (K-major)
    const int bkr = tid >> 5, bn4 = (tid & 31) << 2;    // B loader (N-major rows)
    const float* __restrict__ A = g_sc + (size_t)bh*S_LEN*S_LEN;
    const float* __restrict__ V = vsrc + (size_t)bh*S_LEN*HD;
    const int kmax = m0 + BM;
    float c[4][4][4]; ZERO_C(c);

    float4 ra[4], rb[4];
#pragma unroll
    for (int i=0;i<4;i++){
        ra[i] = *(const float4*)&A[(size_t)(m0+lr+i*32)*S_LEN + lc];
        rb[i] = *(const float4*)&V[(size_t)(bkr+i*8)*HD + bn4];
    }
    for (int kk=0; kk<kmax; kk+=BK){
#pragma unroll
        for (int i=0;i<4;i++){
            const int r = lr + i*32;
            *(float4*)&As[r*LDSM+lc] = make_float4(tf32r(ra[i].x),tf32r(ra[i].y),tf32r(ra[i].z),tf32r(ra[i].w));
            const int kr = bkr + i*8;
            Bs[(bn4+0)*LDSM+kr] = tf32r(rb[i].x);
            Bs[(bn4+1)*LDSM+kr] = tf32r(rb[i].y);
            Bs[(bn4+2)*LDSM+kr] = tf32r(rb[i].z);
            Bs[(bn4+3)*LDSM+kr] = tf32r(rb[i].w);
        }
        __syncthreads();
        if (kk + BK < kmax){
#pragma unroll
            for (int i=0;i<4;i++){
                ra[i] = *(const float4*)&A[(size_t)(m0+lr+i*32)*S_LEN + kk+BK + lc];
                rb[i] = *(const float4*)&V[(size_t)(kk+BK+bkr+i*8)*HD + bn4];
            }
        }
        mma_tile(As,Bs,c,lane,wm,wn);
        __syncthreads();
    }
    const int g = lane>>2, t = lane&3;
    const int b = bh >> 4, h = bh & 15;
#pragma unroll
    for (int im=0;im<4;im++)
#pragma unroll
    for (int in_=0;in_<4;in_++)
#pragma unroll
    for (int r=0;r<4;r++){
        const int row = m0 + wm + im*16 + g + ((r&2)?8:0);
        const int col = wn + in_*8 + 2*t + (r&1);
        g_o[((size_t)b*S_LEN + row)*EMB + h*HD + col] = tf32r(c[im][in_][r]);
    }
}

// ---------------------------------------------------------------------------
extern "C" void kernel_launch(void* const* d_in, const int* in_sizes, int n_in,
                              void* d_out, int out_size)
{
    (void)in_sizes; (void)n_in; (void)out_size;
    const float* x  = (const float*)d_in[0];
    const float* Wq = (const float*)d_in[1];
    const float* Wk = (const float*)d_in[2];
    const float* Wv = (const float*)d_in[3];
    const float* Wo = (const float*)d_in[4];
    float* out  = (float*)d_out;                    // attn_out (B,S,E)
    float* kout = out  + (size_t)8388608;           // k (B,H,S,D)
    float* vout = kout + (size_t)8388608;           // v (B,H,S,D)

    cudaFuncSetAttribute(qkv2_kernel,   cudaFuncAttributeMaxDynamicSharedMemorySize, V2_SMEM);
    cudaFuncSetAttribute(oproj2_kernel, cudaFuncAttributeMaxDynamicSharedMemorySize, V2_SMEM);

    float* g_x_p; float* g_wr_p;
    cudaGetSymbolAddress((void**)&g_x_p,  g_x);
    cudaGetSymbolAddress((void**)&g_wr_p, g_wr);

    // 0) pre-round inputs to tf32 (rna)
    preround_kernel<<<8192, 256>>>((const float4*)x,  (float4*)g_x_p);
    preround_kernel<<<4096, 256>>>((const float4*)Wq, (float4*)(g_wr_p));
    preround_kernel<<<4096, 256>>>((const float4*)Wk, (float4*)(g_wr_p +  4194304));
    preround_kernel<<<4096, 256>>>((const float4*)Wv, (float4*)(g_wr_p +  8388608));
    preround_kernel<<<4096, 256>>>((const float4*)Wo, (float4*)(g_wr_p + 12582912));

    qkv2_kernel   <<<dim3(EMB/BN, MTOT/BM, 3), 256, V2_SMEM>>>(kout, vout);
    rope_kernel   <<<16384, 256>>>(kout);
    scores_kernel <<<dim3(S_LEN/BN, S_LEN/BM, BHN), 256>>>();
    softmax_kernel<<<BHN*S_LEN, 256>>>();
    pv_kernel     <<<dim3(1, S_LEN/BM, BHN), 256>>>(vout);
    oproj2_kernel <<<dim3(EMB/BN, MTOT/BM), 256, V2_SMEM>>>(out);
}

// round 11
// speedup vs baseline: 1.1795x; 1.1327x over previous
#include <cuda_runtime.h>
#include <cstdint>
#include <cstddef>

#define S_LEN 2048
#define EMB   2048
#define NH    16
#define HD    128
#define NB    2
#define BHN   32            // NB*NH
#define MTOT  4096          // NB*S_LEN

#define BM 128
#define BN 128
#define BK 32
#define LDSM 36             // padded smem stride (floats): conflict-free frag loads

// Scratch (device globals: the sanctioned alloc-free scratch mechanism)
static __device__ float g_q [8388608];     // (B,H,S,D) rope'd q
static __device__ float g_k [8388608];     // (B,H,S,D) rope'd k
static __device__ float g_o [8388608];     // (B,S,E)   attention out (pre Wo)

__device__ __forceinline__ float tf32r(float x){
    unsigned u; asm("cvt.rna.tf32.f32 %0, %1;" : "=r"(u) : "f"(x));
    return __uint_as_float(u);
}
__device__ __forceinline__ float4 tf4(float4 v){
    return make_float4(tf32r(v.x), tf32r(v.y), tf32r(v.z), tf32r(v.w));
}
__device__ __forceinline__ uint32_t smem_u32(const void* p){
    uint32_t a;
    asm("{ .reg .u64 t; cvta.to.shared.u64 t, %1; cvt.u32.u64 %0, t; }" : "=r"(a) : "l"(p));
    return a;
}
__device__ __forceinline__ void mma8(float* c, unsigned a0, unsigned a1, unsigned a2,
                                     unsigned a3, unsigned b0, unsigned b1){
    asm volatile(
        "mma.sync.aligned.m16n8k8.row.col.f32.tf32.tf32.f32 "
        "{%0,%1,%2,%3}, {%4,%5,%6,%7}, {%8,%9}, {%0,%1,%2,%3};\n"
        : "+f"(c[0]), "+f"(c[1]), "+f"(c[2]), "+f"(c[3])
        : "r"(a0), "r"(a1), "r"(a2), "r"(a3), "r"(b0), "r"(b1));
}

// ---------------------------------------------------------------------------
// Projection MMA core: As[128][36], Bs[128][36] hold RAW fp32 ([row][k]);
// tf32 rna rounding applied at fragment load (hidden under HMMA).
// 8 warps, warp tile 64(M) x 32(N); per warp 4x4 m16n8k8 tiles per BK=32 slab.
// ---------------------------------------------------------------------------
__device__ __forceinline__ unsigned ldc(const float* p){
    return __float_as_uint(tf32r(*p));
}
__device__ __forceinline__ void mma_tile_cvt(const float* As, const float* Bs,
                                             float (&c)[4][4][4], int lane, int wm, int wn)
{
    const int g = lane >> 2, t = lane & 3;
#pragma unroll
    for (int ks = 0; ks < 4; ks++){
        const int k0 = ks * 8;
        unsigned a[4][4], b[4][2];
#pragma unroll
        for (int im = 0; im < 4; im++){
            const int r0 = (wm + im*16 + g) * LDSM;
            a[im][0] = ldc(&As[r0          + k0 + t    ]);
            a[im][1] = ldc(&As[r0 + 8*LDSM + k0 + t    ]);
            a[im][2] = ldc(&As[r0          + k0 + t + 4]);
            a[im][3] = ldc(&As[r0 + 8*LDSM + k0 + t + 4]);
        }
#pragma unroll
        for (int in_ = 0; in_ < 4; in_++){
            const int nr = (wn + in_*8 + g) * LDSM;
            b[in_][0] = ldc(&Bs[nr + k0 + t    ]);
            b[in_][1] = ldc(&Bs[nr + k0 + t + 4]);
        }
#pragma unroll
        for (int im = 0; im < 4; im++)
#pragma unroll
            for (int in_ = 0; in_ < 4; in_++)
                mma8(c[im][in_], a[im][0], a[im][1], a[im][2], a[im][3],
                     b[in_][0], b[in_][1]);
    }
}

#define ZERO_C(c) \
    _Pragma("unroll") for (int zi=0; zi<4; zi++) \
    _Pragma("unroll") for (int zj=0; zj<4; zj++) \
    _Pragma("unroll") for (int zr=0; zr<4; zr++) c[zi][zj][zr] = 0.f;

// ===========================================================================
// v2 projection-GEMM core: C[128,128] = A[128,2048] * B[128,2048]^T
// cp.async 3-stage pipeline (raw fp32), one barrier/slab, 2 CTAs/SM.
// ===========================================================================
#define V2_STG_A 18432
#define V2_STG   36864
#define V2_SMEM  110592
#define V2_NKT   64

__device__ __forceinline__ void cp16(uint32_t dst, const float* src){
    asm volatile("cp.async.cg.shared.global [%0], [%1], 16;" :: "r"(dst), "l"(src) : "memory");
}
__device__ __forceinline__ void cp_commit(){ asm volatile("cp.async.commit_group;" ::: "memory"); }
__device__ __forceinline__ void cp_wait1(){ asm volatile("cp.async.wait_group 1;" ::: "memory"); }

__device__ __forceinline__ void v2_issue(uint32_t sbase, int stage,
                                         const float* Ap, const float* Bp, int tid){
    const uint32_t sa = sbase + stage * V2_STG;
    const uint32_t sb = sa + V2_STG_A;
#pragma unroll
    for (int i = 0; i < 4; i++){
        const int idx = tid + i * 256;
        const int row = idx >> 3, c4 = idx & 7;
        cp16(sa + row*144 + c4*16, Ap + (size_t)row * EMB + c4*4);
        cp16(sb + row*144 + c4*16, Bp + (size_t)row * EMB + c4*4);
    }
}

__device__ __forceinline__ void v2_mainloop(const float* __restrict__ A,
                                            const float* __restrict__ B,
                                            float (&c)[4][4][4], char* smem,
                                            int tid, int lane, int wm, int wn)
{
    const uint32_t sbase = smem_u32(smem);
    v2_issue(sbase, 0, A,       B,       tid); cp_commit();
    v2_issue(sbase, 1, A + BK,  B + BK,  tid); cp_commit();
    int st = 0, st2 = 2;
    for (int kt = 0; kt < V2_NKT; kt++){
        cp_wait1();                 // stage kt resident
        __syncthreads();
        const float* As = (const float*)(smem + st * V2_STG);
        const float* Bs = As + V2_STG_A / 4;
        mma_tile_cvt(As, Bs, c, lane, wm, wn);
        if (kt + 2 < V2_NKT)
            v2_issue(sbase, st2, A + (kt+2)*BK, B + (kt+2)*BK, tid);
        cp_commit();                // empty group at tail keeps wait math uniform
        st  = (st  == 2) ? 0 : st  + 1;
        st2 = (st2 == 2) ? 0 : st2 + 1;
    }
}

// ---------------------------------------------------------------------------
// 1) QKV projection (grid.z selects W). Writes (B,H,S,D):
//    q -> g_q, k -> d_out k-region, v -> d_out v-region.
// ---------------------------------------------------------------------------
__global__ void __launch_bounds__(256,2) qkv2_kernel(
    const float* __restrict__ x, const float* __restrict__ Wq,
    const float* __restrict__ Wk, const float* __restrict__ Wv,
    float* __restrict__ kout, float* __restrict__ vout)
{
    extern __shared__ char smem[];
    const int tid = threadIdx.x, lane = tid & 31, w = tid >> 5;
    const int wm = (w>>2)*64, wn = (w&3)*32;
    const int n0 = blockIdx.x*BN, m0 = blockIdx.y*BM, widx = blockIdx.z;
    const float* A = x + (size_t)m0 * EMB;
    const float* W = ((widx==0)?Wq:((widx==1)?Wk:Wv)) + (size_t)n0 * EMB;
    float c[4][4][4]; ZERO_C(c);
    v2_mainloop(A, W, c, smem, tid, lane, wm, wn);

    const int g = lane>>2, t = lane&3;
#pragma unroll
    for (int im=0;im<4;im++)
#pragma unroll
    for (int in_=0;in_<4;in_++)
#pragma unroll
    for (int r=0;r<4;r++){
        const int row = m0 + wm + im*16 + g + ((r&2)?8:0);
        const int col = n0 + wn + in_*8 + 2*t + (r&1);
        const int b = row >> 11, s = row & (S_LEN-1);
        const int h = col >> 7,  d = col & (HD-1);
        const size_t dst = (((size_t)(b*NH+h))*S_LEN + s)*HD + d;
        const float v = c[im][in_][r];
        if      (widx==0) g_q[dst] = v;
        else if (widx==1) kout[dst] = v;
        else              vout[dst] = v;
    }
}

// ---------------------------------------------------------------------------
// 4) Output projection: attn_out = g_o @ Wo^T -> d_out[0 : B*S*E]
// ---------------------------------------------------------------------------
__global__ void __launch_bounds__(256,2) oproj2_kernel(const float* __restrict__ Wo,
                                                       float* __restrict__ out)
{
    extern __shared__ char smem[];
    const int tid = threadIdx.x, lane = tid & 31, w = tid >> 5;
    const int wm = (w>>2)*64, wn = (w&3)*32;
    const int n0 = blockIdx.x*BN, m0 = blockIdx.y*BM;
    const float* A = g_o + (size_t)m0 * EMB;
    const float* B = Wo  + (size_t)n0 * EMB;
    float c[4][4][4]; ZERO_C(c);
    v2_mainloop(A, B, c, smem, tid, lane, wm, wn);

    const int g = lane>>2, t = lane&3;
#pragma unroll
    for (int im=0;im<4;im++)
#pragma unroll
    for (int in_=0;in_<4;in_++)
#pragma unroll
    for (int r=0;r<4;r++){
        const int row = m0 + wm + im*16 + g + ((r&2)?8:0);
        const int col = n0 + wn + in_*8 + 2*t + (r&1);
        out[(size_t)row*EMB + col] = c[im][in_][r];
    }
}

// ---------------------------------------------------------------------------
// 2) RoPE: in-place on g_q; kin (raw k in d_out) -> g_k (rope'd).
// ---------------------------------------------------------------------------
__global__ void __launch_bounds__(256) rope_kernel(const float* __restrict__ kin)
{
    const int idx = blockIdx.x*256 + threadIdx.x;      // < B*H*S*(D/2)
    const int j  = idx & 63;
    const int s  = (idx >> 6) & (S_LEN-1);
    const int bh = idx >> 17;
    const float e = (float)(2*j) * (1.0f/128.0f);
    const float invf = (float)exp2(-(double)e * 13.287712379549449); // 10000^-e
    const float ang  = (float)s * invf;
    const double angd = (double)ang;
    const double kq = rint(angd * 0.15915494309189535);  // 1/(2*pi)
    const float rr = (float)(angd - kq * 6.283185307179586);
    float sn, cs;
    __sincosf(rr, &sn, &cs);
    const size_t base = (((size_t)bh)*S_LEN + s)*HD + 2*j;
    float x1 = g_q[base], x2 = g_q[base+1];
    g_q[base]   = x1*cs - x2*sn;
    g_q[base+1] = x1*sn + x2*cs;
    x1 = kin[base]; x2 = kin[base+1];
    g_k[base]   = x1*cs - x2*sn;
    g_k[base+1] = x1*sn + x2*cs;
}

// ===========================================================================
// 3) Flash attention: scores + online softmax + PV fused.
// Per (bh, m-tile of 128 rows). 8 warps; warp tile = 16 rows x full 128 cols.
// smem: Q[128][132] persistent; KP[128][132] (K tile, then P); VT[128][132]
// (V transposed: [d][kpos]). 202,752 B dynamic smem, 1 CTA/SM.
// Writes g_o (B,S,E) raw fp32.
// ===========================================================================
#define FA_STR  132
#define FA_TILE (128*FA_STR)
#define FA_SMEM (3*FA_TILE*4)

__global__ void __launch_bounds__(256) flash_kernel(const float* __restrict__ vsrc)
{
    extern __shared__ float fs[];
    float* Qs = fs;
    float* KP = fs + FA_TILE;
    float* VT = fs + 2*FA_TILE;
    const int tid = threadIdx.x, lane = tid & 31, w = tid >> 5;
    const int g = lane >> 2, t = lane & 3;
    const int mi = 15 - blockIdx.x;          // big tiles first
    const int bh = blockIdx.y;
    const int m0 = mi * 128;
    const float* Qp = g_q + (size_t)bh * S_LEN * HD;
    const float* Kp = g_k + (size_t)bh * S_LEN * HD;
    const float* Vp = vsrc + (size_t)bh * S_LEN * HD;

    // Q tile (tf32-rounded)
#pragma unroll
    for (int i = 0; i < 16; i++){
        const int idx = tid + i*256;
        const int row = idx >> 5, c4 = (idx & 31) << 2;
        *(float4*)&Qs[row*FA_STR + c4] = tf4(*(const float4*)&Qp[(size_t)(m0+row)*HD + c4]);
    }

    float mr0 = -3.0e38f, mr1 = -3.0e38f, l0 = 0.f, l1 = 0.f;
    float o[16][4];
#pragma unroll
    for (int n = 0; n < 16; n++){ o[n][0]=0.f; o[n][1]=0.f; o[n][2]=0.f; o[n][3]=0.f; }

    const int lr0 = w*16 + g, lr1 = lr0 + 8;   // warp-local rows in tile
    const int ar0 = lr0 * FA_STR, ar1 = lr1 * FA_STR;
    const float scale = 0.08838834764831843f;  // 1/sqrt(128)

    for (int j = 0; j <= mi; j++){
        __syncthreads();   // protect KP/VT from prior iteration's readers
        // K tile (tf32-rounded)
#pragma unroll
        for (int i = 0; i < 16; i++){
            const int idx = tid + i*256;
            const int row = idx >> 5, c4 = (idx & 31) << 2;
            *(float4*)&KP[row*FA_STR + c4] = tf4(*(const float4*)&Kp[(size_t)(j*128+row)*HD + c4]);
        }
        // V tile transposed: VT[d][kpos]
#pragma unroll
        for (int i = 0; i < 16; i++){
            const int idx = tid + i*256;
            const int kpos = idx & 127, d4 = (idx >> 7) << 2;
            float4 v = tf4(*(const float4*)&Vp[(size_t)(j*128+kpos)*HD + d4]);
            VT[(d4+0)*FA_STR + kpos] = v.x;
            VT[(d4+1)*FA_STR + kpos] = v.y;
            VT[(d4+2)*FA_STR + kpos] = v.z;
            VT[(d4+3)*FA_STR + kpos] = v.w;
        }
        __syncthreads();

        // S = Q @ K^T  (warp: 16 rows x 128 cols)
        float cs[16][4];
#pragma unroll
        for (int n = 0; n < 16; n++){ cs[n][0]=0.f; cs[n][1]=0.f; cs[n][2]=0.f; cs[n][3]=0.f; }
#pragma unroll
        for (int ks = 0; ks < 16; ks++){
            const int k0 = ks * 8;
            const unsigned a0 = __float_as_uint(Qs[ar0 + k0 + t]);
            const unsigned a1 = __float_as_uint(Qs[ar1 + k0 + t]);
            const unsigned a2 = __float_as_uint(Qs[ar0 + k0 + t + 4]);
            const unsigned a3 = __float_as_uint(Qs[ar1 + k0 + t + 4]);
#pragma unroll
            for (int n = 0; n < 16; n++){
                const int nr = (n*8 + g) * FA_STR;
                mma8(cs[n], a0, a1, a2, a3,
                     __float_as_uint(KP[nr + k0 + t]),
                     __float_as_uint(KP[nr + k0 + t + 4]));
            }
        }
        // scale + causal mask (diagonal tile only)
#pragma unroll
        for (int n = 0; n < 16; n++){
            cs[n][0] *= scale; cs[n][1] *= scale; cs[n][2] *= scale; cs[n][3] *= scale;
        }
        if (j == mi){
#pragma unroll
            for (int n = 0; n < 16; n++){
                const int c0 = n*8 + 2*t, c1 = c0 + 1;
                if (c0 > lr0) cs[n][0] = -3.0e38f;
                if (c1 > lr0) cs[n][1] = -3.0e38f;
                if (c0 > lr1) cs[n][2] = -3.0e38f;
                if (c1 > lr1) cs[n][3] = -3.0e38f;
            }
        }
        // online softmax (rows lr0, lr1; quad = lanes sharing a row)
        float mx0 = -3.0e38f, mx1 = -3.0e38f;
#pragma unroll
        for (int n = 0; n < 16; n++){
            mx0 = fmaxf(mx0, fmaxf(cs[n][0], cs[n][1]));
            mx1 = fmaxf(mx1, fmaxf(cs[n][2], cs[n][3]));
        }
        mx0 = fmaxf(mx0, __shfl_xor_sync(0xffffffffu, mx0, 1));
        mx0 = fmaxf(mx0, __shfl_xor_sync(0xffffffffu, mx0, 2));
        mx1 = fmaxf(mx1, __shfl_xor_sync(0xffffffffu, mx1, 1));
        mx1 = fmaxf(mx1, __shfl_xor_sync(0xffffffffu, mx1, 2));
        const float mn0 = fmaxf(mr0, mx0), mn1 = fmaxf(mr1, mx1);
        const float al0 = __expf(mr0 - mn0), al1 = __expf(mr1 - mn1);
        float s0 = 0.f, s1 = 0.f;
#pragma unroll
        for (int n = 0; n < 16; n++){
            cs[n][0] = __expf(cs[n][0] - mn0); s0 += cs[n][0];
            cs[n][1] = __expf(cs[n][1] - mn0); s0 += cs[n][1];
            cs[n][2] = __expf(cs[n][2] - mn1); s1 += cs[n][2];
            cs[n][3] = __expf(cs[n][3] - mn1); s1 += cs[n][3];
        }
        s0 += __shfl_xor_sync(0xffffffffu, s0, 1);
        s0 += __shfl_xor_sync(0xffffffffu, s0, 2);
        s1 += __shfl_xor_sync(0xffffffffu, s1, 1);
        s1 += __shfl_xor_sync(0xffffffffu, s1, 2);
        l0 = l0*al0 + s0;  l1 = l1*al1 + s1;
        mr0 = mn0;  mr1 = mn1;
#pragma unroll
        for (int n = 0; n < 16; n++){
            o[n][0] *= al0; o[n][1] *= al0; o[n][2] *= al1; o[n][3] *= al1;
        }
        __syncthreads();   // all S-phase reads of KP done before overwrite with P
        // store P (tf32-rounded) into KP: [m-row][kpos]
#pragma unroll
        for (int n = 0; n < 16; n++){
            const int cc = n*8 + 2*t;
            KP[ar0 + cc    ] = tf32r(cs[n][0]);
            KP[ar0 + cc + 1] = tf32r(cs[n][1]);
            KP[ar1 + cc    ] = tf32r(cs[n][2]);
            KP[ar1 + cc + 1] = tf32r(cs[n][3]);
        }
        __syncthreads();
        // O += P @ V   (B = V^T in VT: rows = d, cols = kpos)
#pragma unroll
        for (int ks = 0; ks < 16; ks++){
            const int k0 = ks * 8;
            const unsigned a0 = __float_as_uint(KP[ar0 + k0 + t]);
            const unsigned a1 = __float_as_uint(KP[ar1 + k0 + t]);
            const unsigned a2 = __float_as_uint(KP[ar0 + k0 + t + 4]);
            const unsigned a3 = __float_as_uint(KP[ar1 + k0 + t + 4]);
#pragma unroll
            for (int n = 0; n < 16; n++){
                const int nr = (n*8 + g) * FA_STR;
                mma8(o[n], a0, a1, a2, a3,
                     __float_as_uint(VT[nr + k0 + t]),
                     __float_as_uint(VT[nr + k0 + t + 4]));
            }
        }
    }
    // normalize + write to g_o (B,S,E)
    const float inv0 = 1.0f / l0, inv1 = 1.0f / l1;
    const int b = bh >> 4, h = bh & 15;
    const int row0 = m0 + lr0, row1 = m0 + lr1;
    float* d0 = g_o + ((size_t)b*S_LEN + row0)*EMB + h*HD;
    float* d1 = g_o + ((size_t)b*S_LEN + row1)*EMB + h*HD;
#pragma unroll
    for (int n = 0; n < 16; n++){
        const int cc = n*8 + 2*t;
        d0[cc]   = o[n][0]*inv0;
        d0[cc+1] = o[n][1]*inv0;
        d1[cc]   = o[n][2]*inv1;
        d1[cc+1] = o[n][3]*inv1;
    }
}

// ---------------------------------------------------------------------------
extern "C" void kernel_launch(void* const* d_in, const int* in_sizes, int n_in,
                              void* d_out, int out_size)
{
    (void)in_sizes; (void)n_in; (void)out_size;
    const float* x  = (const float*)d_in[0];
    const float* Wq = (const float*)d_in[1];
    const float* Wk = (const float*)d_in[2];
    const float* Wv = (const float*)d_in[3];
    const float* Wo = (const float*)d_in[4];
    float* out  = (float*)d_out;                    // attn_out (B,S,E)
    float* kout = out  + (size_t)8388608;           // k (B,H,S,D)
    float* vout = kout + (size_t)8388608;           // v (B,H,S,D)

    cudaFuncSetAttribute(qkv2_kernel,   cudaFuncAttributeMaxDynamicSharedMemorySize, V2_SMEM);
    cudaFuncSetAttribute(oproj2_kernel, cudaFuncAttributeMaxDynamicSharedMemorySize, V2_SMEM);
    cudaFuncSetAttribute(flash_kernel,  cudaFuncAttributeMaxDynamicSharedMemorySize, FA_SMEM);

    qkv2_kernel  <<<dim3(EMB/BN, MTOT/BM, 3), 256, V2_SMEM>>>(x, Wq, Wk, Wv, kout, vout);
    rope_kernel  <<<16384, 256>>>(kout);
    flash_kernel <<<dim3(16, BHN), 256, FA_SMEM>>>(vout);
    oproj2_kernel<<<dim3(EMB/BN, MTOT/BM), 256, V2_SMEM>>>(Wo, out);
}

// round 14
// speedup vs baseline: 1.2930x; 1.0963x over previous
#include <cuda_runtime.h>
#include <cstdint>
#include <cstddef>

#define S_LEN 2048
#define EMB   2048
#define NH    16
#define HD    128
#define NB    2
#define BHN   32            // NB*NH
#define MTOT  4096          // NB*S_LEN

#define BM 128
#define BN 128
#define BK 32

// Scratch (device globals: the sanctioned alloc-free scratch mechanism)
static __device__ float g_q [8388608];     // (B,H,S,D) rope'd q (tf32-rounded)
static __device__ float g_k [8388608];     // (B,H,S,D) rope'd k (tf32-rounded)
static __device__ float g_o [8388608];     // (B,S,E)   attn out pre-Wo (tf32-rounded)
static __device__ float g_x [8388608];     // tf32-rounded x
static __device__ float g_wr[16777216];    // tf32-rounded Wq|Wk|Wv|Wo

__device__ __forceinline__ float tf32r(float x){
    unsigned u; asm("cvt.rna.tf32.f32 %0, %1;" : "=r"(u) : "f"(x));
    return __uint_as_float(u);
}
__device__ __forceinline__ float4 tf4(float4 v){
    return make_float4(tf32r(v.x), tf32r(v.y), tf32r(v.z), tf32r(v.w));
}
__device__ __forceinline__ uint32_t smem_u32(const void* p){
    uint32_t a;
    asm("{ .reg .u64 t; cvta.to.shared.u64 t, %1; cvt.u32.u64 %0, t; }" : "=r"(a) : "l"(p));
    return a;
}
__device__ __forceinline__ void mma8(float* c, unsigned a0, unsigned a1, unsigned a2,
                                     unsigned a3, unsigned b0, unsigned b1){
    asm volatile(
        "mma.sync.aligned.m16n8k8.row.col.f32.tf32.tf32.f32 "
        "{%0,%1,%2,%3}, {%4,%5,%6,%7}, {%8,%9}, {%0,%1,%2,%3};\n"
        : "+f"(c[0]), "+f"(c[1]), "+f"(c[2]), "+f"(c[3])
        : "r"(a0), "r"(a1), "r"(a2), "r"(a3), "r"(b0), "r"(b1));
}
// ldmatrix x4: four 8x8 b16 tiles == four 8rows x 4cols fp32 tiles.
__device__ __forceinline__ void ldsm4(unsigned* r, uint32_t a){
    asm volatile("ldmatrix.sync.aligned.m8n8.x4.shared.b16 {%0,%1,%2,%3}, [%4];"
        : "=r"(r[0]), "=r"(r[1]), "=r"(r[2]), "=r"(r[3]) : "r"(a));
}

#define ZERO_C(c) \
    _Pragma("unroll") for (int zi=0; zi<4; zi++) \
    _Pragma("unroll") for (int zj=0; zj<4; zj++) \
    _Pragma("unroll") for (int zr=0; zr<4; zr++) c[zi][zj][zr] = 0.f;

// ===========================================================================
// Projection GEMM core: C[128,128] = A[128,2048] * B[128,2048]^T, inputs
// pre-rounded tf32. cp.async 3-stage pipeline; LDSM fragment loads.
// smem row stride 36 floats (144B): cp.async-compatible + LDSM conflict-free.
// 8 warps, warp tile 64(M) x 32(N).
// ===========================================================================
#define V2_STG_A 18432
#define V2_STG   36864
#define V2_SMEM  110592
#define V2_NKT   64

__device__ __forceinline__ void cp16(uint32_t dst, const float* src){
    asm volatile("cp.async.cg.shared.global [%0], [%1], 16;" :: "r"(dst), "l"(src) : "memory");
}
__device__ __forceinline__ void cp_commit(){ asm volatile("cp.async.commit_group;" ::: "memory"); }
__device__ __forceinline__ void cp_wait1(){ asm volatile("cp.async.wait_group 1;" ::: "memory"); }

__device__ __forceinline__ void v2_issue(uint32_t sbase, int stage,
                                         const float* Ap, const float* Bp, int tid){
    const uint32_t sa = sbase + stage * V2_STG;
    const uint32_t sb = sa + V2_STG_A;
#pragma unroll
    for (int i = 0; i < 4; i++){
        const int idx = tid + i * 256;
        const int row = idx >> 3, c4 = idx & 7;
        cp16(sa + row*144 + c4*16, Ap + (size_t)row * EMB + c4*4);
        cp16(sb + row*144 + c4*16, Bp + (size_t)row * EMB + c4*4);
    }
}

__device__ __forceinline__ void mma_slab_ldsm(uint32_t sa, uint32_t sb, float (&c)[4][4][4])
{
#pragma unroll
    for (int ks = 0; ks < 4; ks++){
        unsigned bb0[4], bb1[4];
        ldsm4(bb0, sb + ks*32);
        ldsm4(bb1, sb + 16*144 + ks*32);
#pragma unroll
        for (int im = 0; im < 4; im++){
            unsigned aa[4];
            ldsm4(aa, sa + im*(16*144) + ks*32);
            mma8(c[im][0], aa[0],aa[1],aa[2],aa[3], bb0[0], bb0[1]);
            mma8(c[im][1], aa[0],aa[1],aa[2],aa[3], bb0[2], bb0[3]);
            mma8(c[im][2], aa[0],aa[1],aa[2],aa[3], bb1[0], bb1[1]);
            mma8(c[im][3], aa[0],aa[1],aa[2],aa[3], bb1[2], bb1[3]);
        }
    }
}

__device__ __forceinline__ void v3_mainloop(const float* __restrict__ A,
                                            const float* __restrict__ B,
                                            float (&c)[4][4][4], char* smem,
                                            int tid, int lane, int wm, int wn)
{
    const uint32_t sbase = smem_u32(smem);
    // A-frag lane base: rows wm+(lane&15), col 4*((lane>>4)&1)
    const uint32_t aoff = (uint32_t)((wm + (lane & 15))*144 + ((lane >> 4) & 1)*16);
    // B-frag lane base: rows wn+(lane&7)+8*((lane>>4)&1), col 4*((lane>>3)&1)
    const uint32_t boff = (uint32_t)(V2_STG_A +
        (wn + (lane & 7) + ((lane >> 4) & 1)*8)*144 + ((lane >> 3) & 1)*16);

    v2_issue(sbase, 0, A,       B,       tid); cp_commit();
    v2_issue(sbase, 1, A + BK,  B + BK,  tid); cp_commit();
    int st = 0, st2 = 2;
    for (int kt = 0; kt < V2_NKT; kt++){
        cp_wait1();
        __syncthreads();
        const uint32_t stg = sbase + st * V2_STG;
        mma_slab_ldsm(stg + aoff, stg + boff, c);
        if (kt + 2 < V2_NKT)
            v2_issue(sbase, st2, A + (kt+2)*BK, B + (kt+2)*BK, tid);
        cp_commit();
        st  = (st  == 2) ? 0 : st  + 1;
        st2 = (st2 == 2) ? 0 : st2 + 1;
    }
}

// ---------------------------------------------------------------------------
// 0) Pre-round fp32 -> tf32 (rna)
// ---------------------------------------------------------------------------
__global__ void __launch_bounds__(256) preround_kernel(const float4* __restrict__ src,
                                                       float4* __restrict__ dst)
{
    const int i = blockIdx.x * 256 + threadIdx.x;
    dst[i] = tf4(src[i]);
}

// ---------------------------------------------------------------------------
// 1) QKV projection (grid.z selects W). Writes (B,H,S,D):
//    q -> g_q (raw; rope rounds later), k -> d_out k-region, v -> d_out v-region.
// ---------------------------------------------------------------------------
__global__ void __launch_bounds__(256,2) qkv2_kernel(float* __restrict__ kout,
                                                     float* __restrict__ vout)
{
    extern __shared__ char smem[];
    const int tid = threadIdx.x, lane = tid & 31, w = tid >> 5;
    const int wm = (w>>2)*64, wn = (w&3)*32;
    const int n0 = blockIdx.x*BN, m0 = blockIdx.y*BM, widx = blockIdx.z;
    const float* A = g_x  + (size_t)m0 * EMB;
    const float* B = g_wr + (size_t)widx * 4194304 + (size_t)n0 * EMB;
    float c[4][4][4]; ZERO_C(c);
    v3_mainloop(A, B, c, smem, tid, lane, wm, wn);

    const int g = lane>>2, t = lane&3;
#pragma unroll
    for (int im=0;im<4;im++)
#pragma unroll
    for (int in_=0;in_<4;in_++)
#pragma unroll
    for (int r=0;r<4;r++){
        const int row = m0 + wm + im*16 + g + ((r&2)?8:0);
        const int col = n0 + wn + in_*8 + 2*t + (r&1);
        const int b = row >> 11, s = row & (S_LEN-1);
        const int h = col >> 7,  d = col & (HD-1);
        const size_t dst = (((size_t)(b*NH+h))*S_LEN + s)*HD + d;
        const float v = c[im][in_][r];
        if      (widx==0) g_q[dst] = v;
        else if (widx==1) kout[dst] = v;
        else              vout[dst] = v;
    }
}

// ---------------------------------------------------------------------------
// 4) Output projection: attn_out = g_o @ Wo^T -> d_out[0 : B*S*E]
// ---------------------------------------------------------------------------
__global__ void __launch_bounds__(256,2) oproj2_kernel(float* __restrict__ out)
{
    extern __shared__ char smem[];
    const int tid = threadIdx.x, lane = tid & 31, w = tid >> 5;
    const int wm = (w>>2)*64, wn = (w&3)*32;
    const int n0 = blockIdx.x*BN, m0 = blockIdx.y*BM;
    const float* A = g_o  + (size_t)m0 * EMB;
    const float* B = g_wr + (size_t)12582912 + (size_t)n0 * EMB;
    float c[4][4][4]; ZERO_C(c);
    v3_mainloop(A, B, c, smem, tid, lane, wm, wn);

    const int g = lane>>2, t = lane&3;
#pragma unroll
    for (int im=0;im<4;im++)
#pragma unroll
    for (int in_=0;in_<4;in_++)
#pragma unroll
    for (int r=0;r<4;r++){
        const int row = m0 + wm + im*16 + g + ((r&2)?8:0);
        const int col = n0 + wn + in_*8 + 2*t + (r&1);
        out[(size_t)row*EMB + col] = c[im][in_][r];
    }
}

// ---------------------------------------------------------------------------
// 2) RoPE: g_q in-place, kin -> g_k; outputs tf32-rounded (flash reads raw).
// ---------------------------------------------------------------------------
__global__ void __launch_bounds__(256) rope_kernel(const float* __restrict__ kin)
{
    const int idx = blockIdx.x*256 + threadIdx.x;      // < B*H*S*(D/2)
    const int j  = idx & 63;
    const int s  = (idx >> 6) & (S_LEN-1);
    const int bh = idx >> 17;
    const float e = (float)(2*j) * (1.0f/128.0f);
    const float invf = (float)exp2(-(double)e * 13.287712379549449); // 10000^-e
    const float ang  = (float)s * invf;
    const double angd = (double)ang;
    const double kq = rint(angd * 0.15915494309189535);  // 1/(2*pi)
    const float rr = (float)(angd - kq * 6.283185307179586);
    float sn, cs;
    __sincosf(rr, &sn, &cs);
    const size_t base = (((size_t)bh)*S_LEN + s)*HD + 2*j;
    float x1 = g_q[base], x2 = g_q[base+1];
    g_q[base]   = tf32r(x1*cs - x2*sn);
    g_q[base+1] = tf32r(x1*sn + x2*cs);
    x1 = kin[base]; x2 = kin[base+1];
    g_k[base]   = tf32r(x1*cs - x2*sn);
    g_k[base+1] = tf32r(x1*sn + x2*cs);
}

// ===========================================================================
// 3) Flash attention: scores + online softmax + PV fused, LDSM fragment path.
// Per (bh, 128-row m-tile). 8 warps; warp tile = 16 rows x 128 cols.
// smem: Q[128][132]; KP[128][132] (K, then P); VT[128][132] (V^T: [d][kpos]).
// Writes g_o (B,S,E) tf32-rounded.
// ===========================================================================
#define FA_STR  132
#define FA_TILE (128*FA_STR)
#define FA_SMEM (3*FA_TILE*4)

__global__ void __launch_bounds__(256) flash_kernel(const float* __restrict__ vsrc)
{
    extern __shared__ float fs[];
    float* Qs = fs;
    float* KP = fs + FA_TILE;
    float* VT = fs + 2*FA_TILE;
    const int tid = threadIdx.x, lane = tid & 31, w = tid >> 5;
    const int g = lane >> 2, t = lane & 3;
    const int mi = 15 - blockIdx.x;          // big tiles first
    const int bh = blockIdx.y;
    const int m0 = mi * 128;
    const float* Qp = g_q + (size_t)bh * S_LEN * HD;
    const float* Kp = g_k + (size_t)bh * S_LEN * HD;
    const float* Vp = vsrc + (size_t)bh * S_LEN * HD;

    const uint32_t fsb = smem_u32(fs);
    // A-frag lane base (rows w*16+(lane&15), col 4*((lane>>4)&1)); stride 528B
    const uint32_t laneA = (uint32_t)((w*16 + (lane & 15))*528 + ((lane >> 4) & 1)*16);
    // B-frag lane base (rows (lane&7)+8*((lane>>4)&1), col 4*((lane>>3)&1))
    const uint32_t laneB = (uint32_t)(((lane & 7) + ((lane >> 4) & 1)*8)*528 + ((lane >> 3) & 1)*16);
    const uint32_t qA  = fsb + laneA;                       // Q as A
    const uint32_t pA  = fsb + FA_TILE*4 + laneA;           // P as A
    const uint32_t kB  = fsb + FA_TILE*4 + laneB;           // K as B
    const uint32_t vB  = fsb + 2*FA_TILE*4 + laneB;         // V^T as B

    // Q tile (already tf32-rounded by rope)
#pragma unroll
    for (int i = 0; i < 16; i++){
        const int idx = tid + i*256;
        const int row = idx >> 5, c4 = (idx & 31) << 2;
        *(float4*)&Qs[row*FA_STR + c4] = *(const float4*)&Qp[(size_t)(m0+row)*HD + c4];
    }

    float mr0 = -3.0e38f, mr1 = -3.0e38f, l0 = 0.f, l1 = 0.f;
    float o[16][4];
#pragma unroll
    for (int n = 0; n < 16; n++){ o[n][0]=0.f; o[n][1]=0.f; o[n][2]=0.f; o[n][3]=0.f; }

    const int lr0 = w*16 + g, lr1 = lr0 + 8;
    const int ar0 = lr0 * FA_STR, ar1 = lr1 * FA_STR;
    const float scale = 0.08838834764831843f;  // 1/sqrt(128)

    for (int j = 0; j <= mi; j++){
        __syncthreads();
        // K tile (pre-rounded)
#pragma unroll
        for (int i = 0; i < 16; i++){
            const int idx = tid + i*256;
            const int row = idx >> 5, c4 = (idx & 31) << 2;
            *(float4*)&KP[row*FA_STR + c4] = *(const float4*)&Kp[(size_t)(j*128+row)*HD + c4];
        }
        // V tile transposed + rounded: VT[d][kpos]
#pragma unroll
        for (int i = 0; i < 16; i++){
            const int idx = tid + i*256;
            const int kpos = idx & 127, d4 = (idx >> 7) << 2;
            float4 v = tf4(*(const float4*)&Vp[(size_t)(j*128+kpos)*HD + d4]);
            VT[(d4+0)*FA_STR + kpos] = v.x;
            VT[(d4+1)*FA_STR + kpos] = v.y;
            VT[(d4+2)*FA_STR + kpos] = v.z;
            VT[(d4+3)*FA_STR + kpos] = v.w;
        }
        __syncthreads();

        // S = Q @ K^T
        float cs[16][4];
#pragma unroll
        for (int n = 0; n < 16; n++){ cs[n][0]=0.f; cs[n][1]=0.f; cs[n][2]=0.f; cs[n][3]=0.f; }
#pragma unroll
        for (int ks = 0; ks < 16; ks++){
            unsigned aa[4];
            ldsm4(aa, qA + ks*32);
#pragma unroll
            for (int p = 0; p < 8; p++){
                unsigned bb[4];
                ldsm4(bb, kB + p*(16*528) + ks*32);
                mma8(cs[2*p  ], aa[0],aa[1],aa[2],aa[3], bb[0], bb[1]);
                mma8(cs[2*p+1], aa[0],aa[1],aa[2],aa[3], bb[2], bb[3]);
            }
        }
        // scale + causal mask (diagonal tile only)
#pragma unroll
        for (int n = 0; n < 16; n++){
            cs[n][0] *= scale; cs[n][1] *= scale; cs[n][2] *= scale; cs[n][3] *= scale;
        }
        if (j == mi){
#pragma unroll
            for (int n = 0; n < 16; n++){
                const int c0 = n*8 + 2*t, c1 = c0 + 1;
                if (c0 > lr0) cs[n][0] = -3.0e38f;
                if (c1 > lr0) cs[n][1] = -3.0e38f;
                if (c0 > lr1) cs[n][2] = -3.0e38f;
                if (c1 > lr1) cs[n][3] = -3.0e38f;
            }
        }
        // online softmax (rows lr0, lr1)
        float mx0 = -3.0e38f, mx1 = -3.0e38f;
#pragma unroll
        for (int n = 0; n < 16; n++){
            mx0 = fmaxf(mx0, fmaxf(cs[n][0], cs[n][1]));
            mx1 = fmaxf(mx1, fmaxf(cs[n][2], cs[n][3]));
        }
        mx0 = fmaxf(mx0, __shfl_xor_sync(0xffffffffu, mx0, 1));
        mx0 = fmaxf(mx0, __shfl_xor_sync(0xffffffffu, mx0, 2));
        mx1 = fmaxf(mx1, __shfl_xor_sync(0xffffffffu, mx1, 1));
        mx1 = fmaxf(mx1, __shfl_xor_sync(0xffffffffu, mx1, 2));
        const float mn0 = fmaxf(mr0, mx0), mn1 = fmaxf(mr1, mx1);
        const float al0 = __expf(mr0 - mn0), al1 = __expf(mr1 - mn1);
        float s0 = 0.f, s1 = 0.f;
#pragma unroll
        for (int n = 0; n < 16; n++){
            cs[n][0] = __expf(cs[n][0] - mn0); s0 += cs[n][0];
            cs[n][1] = __expf(cs[n][1] - mn0); s0 += cs[n][1];
            cs[n][2] = __expf(cs[n][2] - mn1); s1 += cs[n][2];
            cs[n][3] = __expf(cs[n][3] - mn1); s1 += cs[n][3];
        }
        s0 += __shfl_xor_sync(0xffffffffu, s0, 1);
        s0 += __shfl_xor_sync(0xffffffffu, s0, 2);
        s1 += __shfl_xor_sync(0xffffffffu, s1, 1);
        s1 += __shfl_xor_sync(0xffffffffu, s1, 2);
        l0 = l0*al0 + s0;  l1 = l1*al1 + s1;
        mr0 = mn0;  mr1 = mn1;
#pragma unroll
        for (int n = 0; n < 16; n++){
            o[n][0] *= al0; o[n][1] *= al0; o[n][2] *= al1; o[n][3] *= al1;
        }
        __syncthreads();   // all S-phase reads of KP done before overwrite with P
        // store P (tf32-rounded) into KP: [m-row][kpos]
#pragma unroll
        for (int n = 0; n < 16; n++){
            const int cc = n*8 + 2*t;
            KP[ar0 + cc    ] = tf32r(cs[n][0]);
            KP[ar0 + cc + 1] = tf32r(cs[n][1]);
            KP[ar1 + cc    ] = tf32r(cs[n][2]);
            KP[ar1 + cc + 1] = tf32r(cs[n][3]);
        }
        __syncthreads();
        // O += P @ V
#pragma unroll
        for (int ks = 0; ks < 16; ks++){
            unsigned aa[4];
            ldsm4(aa, pA + ks*32);
#pragma unroll
            for (int p = 0; p < 8; p++){
                unsigned bb[4];
                ldsm4(bb, vB + p*(16*528) + ks*32);
                mma8(o[2*p  ], aa[0],aa[1],aa[2],aa[3], bb[0], bb[1]);
                mma8(o[2*p+1], aa[0],aa[1],aa[2],aa[3], bb[2], bb[3]);
            }
        }
    }
    // normalize + write to g_o (B,S,E), tf32-rounded for oproj
    const float inv0 = 1.0f / l0, inv1 = 1.0f / l1;
    const int b = bh >> 4, h = bh & 15;
    const int row0 = m0 + lr0, row1 = m0 + lr1;
    float* d0 = g_o + ((size_t)b*S_LEN + row0)*EMB + h*HD;
    float* d1 = g_o + ((size_t)b*S_LEN + row1)*EMB + h*HD;
#pragma unroll
    for (int n = 0; n < 16; n++){
        const int cc = n*8 + 2*t;
        d0[cc]   = tf32r(o[n][0]*inv0);
        d0[cc+1] = tf32r(o[n][1]*inv0);
        d1[cc]   = tf32r(o[n][2]*inv1);
        d1[cc+1] = tf32r(o[n][3]*inv1);
    }
}

// ---------------------------------------------------------------------------
extern "C" void kernel_launch(void* const* d_in, const int* in_sizes, int n_in,
                              void* d_out, int out_size)
{
    (void)in_sizes; (void)n_in; (void)out_size;
    const float* x  = (const float*)d_in[0];
    const float* Wq = (const float*)d_in[1];
    const float* Wk = (const float*)d_in[2];
    const float* Wv = (const float*)d_in[3];
    const float* Wo = (const float*)d_in[4];
    float* out  = (float*)d_out;                    // attn_out (B,S,E)
    float* kout = out  + (size_t)8388608;           // k (B,H,S,D)
    float* vout = kout + (size_t)8388608;           // v (B,H,S,D)

    cudaFuncSetAttribute(qkv2_kernel,   cudaFuncAttributeMaxDynamicSharedMemorySize, V2_SMEM);
    cudaFuncSetAttribute(oproj2_kernel, cudaFuncAttributeMaxDynamicSharedMemorySize, V2_SMEM);
    cudaFuncSetAttribute(flash_kernel,  cudaFuncAttributeMaxDynamicSharedMemorySize, FA_SMEM);

    float* g_x_p; float* g_wr_p;
    cudaGetSymbolAddress((void**)&g_x_p,  g_x);
    cudaGetSymbolAddress((void**)&g_wr_p, g_wr);

    preround_kernel<<<8192, 256>>>((const float4*)x,  (float4*)g_x_p);
    preround_kernel<<<4096, 256>>>((const float4*)Wq, (float4*)(g_wr_p));
    preround_kernel<<<4096, 256>>>((const float4*)Wk, (float4*)(g_wr_p +  4194304));
    preround_kernel<<<4096, 256>>>((const float4*)Wv, (float4*)(g_wr_p +  8388608));
    preround_kernel<<<4096, 256>>>((const float4*)Wo, (float4*)(g_wr_p + 12582912));

    qkv2_kernel  <<<dim3(EMB/BN, MTOT/BM, 3), 256, V2_SMEM>>>(kout, vout);
    rope_kernel  <<<16384, 256>>>(kout);
    flash_kernel <<<dim3(16, BHN), 256, FA_SMEM>>>(vout);
    oproj2_kernel<<<dim3(EMB/BN, MTOT/BM), 256, V2_SMEM>>>(out);
}